// round 15
// baseline (speedup 1.0000x reference)
#include <cuda_runtime.h>
#include <cuda_fp16.h>
#include <cstdint>

typedef __half f16;

#define NTOK 22016   // 512*43
#define NB   512
#define TT   43
#define HD   128
#define DK   96
#define DKP  97
#define SSP  44
#define DFF  2048
#define OUTV 8000
#define QKVW 576
#define LNEPS 1e-5f

// source (input) packed weight offsets
#define SRC_PROJ 73728
#define SRC_FF1  98304
#define SRC_FF2  360448
#define SRC_FIN  622592
#define SRC_TOT  1646592

// destination layout in g_wh (tile-aligned; QKV/FF1/FIN swizzled-tiled, PROJ/FF2 plain)
#define TILE_ELEMS 16384
#define TILE_BYTES 32768
#define W_QKV  0          // 5 tiles  (576 rows -> 640 padded)
#define W_PROJ 81920      // plain 24576
#define W_FF1  114688     // 16 tiles (2048 rows)
#define W_FF2  376832     // plain 262144
#define W_FIN  638976     // 63 tiles (8000 rows -> 8064 padded)
#define W_TOT  1671168

// XOR swizzle for 256B rows: bits[4:7) ^= bits[8:11)
#define SWZ(x) ((x) ^ ((((x) >> 8) & 7) << 4))

// ---------------- scratch (device globals) ----------------
__device__ float g_x0 [NTOK * HD];
__device__ f16   g_x0h[NTOK * HD];          // swizzled-tiled
__device__ float g_qkv[NTOK * QKVW];
__device__ float g_bqkv[QKVW];
__device__ f16   g_h12h[NTOK * 2 * DK];     // plain
__device__ float g_mho[NTOK * HD];
__device__ float g_x1 [NTOK * HD];
__device__ f16   g_x1h[NTOK * HD];          // swizzled-tiled
__device__ f16   g_ffhh[NTOK * DFF];        // plain
__device__ float g_ff2[NTOK * HD];
__device__ f16   g_x2h[NTOK * HD];          // swizzled-tiled
__device__ f16   g_wh[W_TOT];

// ---------------- helpers ----------------
__device__ __forceinline__ uint32_t smem_u32(const void* p) {
    return (uint32_t)__cvta_generic_to_shared(p);
}

#define LDMX4(R, ADDR) \
    asm volatile("ldmatrix.sync.aligned.m8n8.x4.shared.b16 {%0,%1,%2,%3},[%4];\n" \
        : "=r"((R)[0]), "=r"((R)[1]), "=r"((R)[2]), "=r"((R)[3]) : "r"(ADDR))

#define MMA16816(C, A, B0, B1) \
    asm volatile("mma.sync.aligned.m16n8k16.row.col.f32.f16.f16.f32 " \
        "{%0,%1,%2,%3},{%4,%5,%6,%7},{%8,%9},{%0,%1,%2,%3};\n" \
        : "+f"((C)[0]), "+f"((C)[1]), "+f"((C)[2]), "+f"((C)[3]) \
        : "r"((A)[0]), "r"((A)[1]), "r"((A)[2]), "r"((A)[3]), "r"(B0), "r"(B1))

__device__ __forceinline__ void cpa16(uint32_t saddr, const void* gaddr, int srcsz) {
    asm volatile("cp.async.cg.shared.global [%0], [%1], 16, %2;\n"
                 :: "r"(saddr), "l"(gaddr), "r"(srcsz) : "memory");
}
#define CPA_COMMIT() asm volatile("cp.async.commit_group;\n" ::: "memory")
#define CPA_WAITG(n) asm volatile("cp.async.wait_group %0;\n" :: "n"(n) : "memory")

__device__ __forceinline__ void mb_init(uint32_t mb) {
    asm volatile("mbarrier.init.shared.b64 [%0], 1;" :: "r"(mb) : "memory");
}
__device__ __forceinline__ void mb_wait(uint32_t mb, unsigned ph) {
    unsigned done = 0;
    while (!done)
        asm volatile("{\n\t.reg .pred p;\n\t"
                     "mbarrier.test_wait.parity.shared.b64 p, [%1], %2;\n\t"
                     "selp.u32 %0, 1, 0, p;\n\t}"
                     : "=r"(done) : "r"(mb), "r"(ph) : "memory");
}
__device__ __forceinline__ void bulk_cp(uint32_t saddr, const void* gaddr, uint32_t mb) {
    asm volatile("mbarrier.arrive.expect_tx.shared.b64 _, [%0], %1;"
                 :: "r"(mb), "r"((uint32_t)TILE_BYTES) : "memory");
    asm volatile("cp.async.bulk.shared::cta.global.mbarrier::complete_tx::bytes "
                 "[%0], [%1], %2, [%3];"
                 :: "r"(saddr), "l"(gaddr), "r"((uint32_t)TILE_BYTES), "r"(mb) : "memory");
}

// ============ streaming bulk-copy GEMM for K=128: Y = X @ W^T + b ============
// B tile resident per CTA; strip of A m-tiles streamed via double-buffered bulk copies.
// A,B pre-swizzled tile-major in gmem. 256 threads (8 warps 2x4), warp tile 64x32.
// smem = 3 tiles + barriers ~ 96KB -> 2 CTAs/SM.
#define K128S_SMEM (3 * TILE_BYTES + 64)

template<int OUT_MODE>
__global__ __launch_bounds__(256, 2)
void gemm_k128s(const f16* __restrict__ A, const f16* __restrict__ B,
                const float* __restrict__ bias,
                float* __restrict__ Yf, f16* __restrict__ Yh,
                int M, int O, int mSplit) {
    extern __shared__ char smem[];
    const uint32_t sB  = smem_u32(smem);
    const uint32_t sA  = sB + TILE_BYTES;            // 2 slots
    const uint32_t mbB = sB + 3 * TILE_BYTES;
    const uint32_t mbA = mbB + 8;                    // [2]
    const int tid = threadIdx.x;
    const int wid = tid >> 5, lane = tid & 31;
    const int wm = wid & 1, wn = wid >> 1;           // 2 x 4 warps, warp tile 64x32
    const int n0 = blockIdx.x << 7;
    const int nTiles = M >> 7;
    const int t0 = (int)((long)nTiles * blockIdx.y / mSplit);
    const int t1 = (int)((long)nTiles * (blockIdx.y + 1) / mSplit);

    if (tid == 0) { mb_init(mbB); mb_init(mbA); mb_init(mbA + 8); }
    __syncthreads();
    if (tid == 0) {
        bulk_cp(sB, B + (size_t)blockIdx.x * TILE_ELEMS, mbB);
        bulk_cp(sA, A + (size_t)t0 * TILE_ELEMS, mbA);
        if (t0 + 1 < t1)
            bulk_cp(sA + TILE_BYTES, A + (size_t)(t0 + 1) * TILE_ELEMS, mbA + 8);
    }
    mb_wait(mbB, 0);

    unsigned ph0 = 0, ph1 = 0;

    for (int t = t0; t < t1; t++) {
        int s = (t - t0) & 1;
        if (s == 0) { mb_wait(mbA, ph0); ph0 ^= 1; }
        else        { mb_wait(mbA + 8, ph1); ph1 ^= 1; }
        uint32_t sAs = sA + (uint32_t)s * TILE_BYTES;

        float acc[4][4][4];
#pragma unroll
        for (int a = 0; a < 4; a++)
#pragma unroll
            for (int b = 0; b < 4; b++)
#pragma unroll
                for (int c = 0; c < 4; c++) acc[a][b][c] = 0.f;

#pragma unroll
        for (int ks = 0; ks < 128; ks += 16) {
            unsigned ah[4][4], bh[2][4];
#pragma unroll
            for (int mt = 0; mt < 4; mt++) {
                int row = wm * 64 + mt * 16 + (lane & 15);
                int cb = (ks + (lane >> 4) * 8) * 2;
                LDMX4(ah[mt], sAs + SWZ(row * 256 + cb));
            }
#pragma unroll
            for (int nt = 0; nt < 2; nt++) {
                int row = wn * 32 + nt * 16 + (lane & 7) + ((lane >> 4) << 3);
                int cb = (ks + ((lane >> 3) & 1) * 8) * 2;
                LDMX4(bh[nt], sB + SWZ(row * 256 + cb));
            }
#pragma unroll
            for (int mt = 0; mt < 4; mt++) {
#pragma unroll
                for (int nf = 0; nf < 4; nf++) {
                    int nt = nf >> 1, q = (nf & 1) * 2;
                    MMA16816(acc[mt][nf], ah[mt], bh[nt][q], bh[nt][q + 1]);
                }
            }
        }

        __syncthreads();                         // all warps done reading slot s
        if (tid == 0 && t + 2 < t1)
            bulk_cp(sAs, A + (size_t)(t + 2) * TILE_ELEMS, s == 0 ? mbA : mbA + 8);

        // epilogue (overlaps the in-flight copy)
        int m0 = t << 7;
#pragma unroll
        for (int mt = 0; mt < 4; mt++) {
#pragma unroll
            for (int nf = 0; nf < 4; nf++) {
                int col = n0 + wn * 32 + nf * 8 + (lane & 3) * 2;
                if (col >= O) continue;
                int row0 = m0 + wm * 64 + mt * 16 + (lane >> 2);
                float bi0 = bias[col], bi1 = bias[col + 1];
#pragma unroll
                for (int i = 0; i < 2; i++) {
                    size_t r = row0 + i * 8;
                    float v0 = acc[mt][nf][i * 2 + 0] + bi0;
                    float v1 = acc[mt][nf][i * 2 + 1] + bi1;
                    if (OUT_MODE == 0) {
                        *(float2*)&Yf[r * O + col] = make_float2(v0, v1);
                    } else {
                        v0 = fmaxf(v0, 0.f); v1 = fmaxf(v1, 0.f);
                        *(__half2*)&Yh[r * O + col] =
                            __halves2half2(__float2half(v0), __float2half(v1));
                    }
                }
            }
        }
    }
}

// ============ generic pipelined fp16 GEMM (K=192 proj / K=2048 FF2), plain inputs ============
#define ROWB   144
#define B_OFF  18432
#define STAGE  36864
#define SMEM_BYTES (2 * STAGE)

template<int OUT_MODE>
__global__ __launch_bounds__(256, 2)
void gemm_bt(const f16* __restrict__ Ah, const f16* __restrict__ Bh,
             const float* __restrict__ bias,
             float* __restrict__ Yf, f16* __restrict__ Yh,
             int M, int K, int O) {
    extern __shared__ char smem[];
    const uint32_t sbd = smem_u32(smem);
    const int tid = threadIdx.x;
    const int wid = tid >> 5, lane = tid & 31;
    const int wm = wid & 1, wn = wid >> 1;       // 2 x 4 warps, warp tile 64x32
    const int m0 = blockIdx.y << 7;
    const int n0 = blockIdx.x << 7;
    const int nk = K >> 6;

    float acc[4][4][4];
#pragma unroll
    for (int a = 0; a < 4; a++)
#pragma unroll
        for (int b = 0; b < 4; b++)
#pragma unroll
            for (int c = 0; c < 4; c++) acc[a][b][c] = 0.f;

    auto load_chunk = [&](int c) {
        uint32_t stage = sbd + (c & 1) * STAGE;
        int kk = c << 6;
#pragma unroll
        for (int i = 0; i < 4; i++) {
            int idx = tid + (i << 8);
            int row = idx >> 3, c8 = idx & 7;
            cpa16(stage + row * ROWB + c8 * 16, Ah + (size_t)(m0 + row) * K + kk + c8 * 8, 16);
        }
#pragma unroll
        for (int i = 0; i < 4; i++) {
            int idx = tid + (i << 8);
            int row = idx >> 3, c8 = idx & 7;
            int gr = n0 + row;
            int sz = 16;
            if (gr >= O) { sz = 0; gr = 0; }
            cpa16(stage + B_OFF + row * ROWB + c8 * 16, Bh + (size_t)gr * K + kk + c8 * 8, sz);
        }
        CPA_COMMIT();
    };

    load_chunk(0);
    load_chunk(1);

    for (int c = 0; c < nk; c++) {
        if (c < nk - 1) { CPA_WAITG(1); } else { CPA_WAITG(0); }
        __syncthreads();

        uint32_t stage = sbd + (c & 1) * STAGE;
#pragma unroll
        for (int ks = 0; ks < 64; ks += 16) {
            unsigned ah[4][4], bh[2][4];
#pragma unroll
            for (int mt = 0; mt < 4; mt++) {
                int row = wm * 64 + mt * 16 + (lane & 15);
                int cb = (ks + (lane >> 4) * 8) * 2;
                LDMX4(ah[mt], stage + row * ROWB + cb);
            }
#pragma unroll
            for (int nt = 0; nt < 2; nt++) {
                int row = wn * 32 + nt * 16 + (lane & 7) + ((lane >> 4) << 3);
                int cb = (ks + ((lane >> 3) & 1) * 8) * 2;
                LDMX4(bh[nt], stage + B_OFF + row * ROWB + cb);
            }
#pragma unroll
            for (int mt = 0; mt < 4; mt++) {
#pragma unroll
                for (int nf = 0; nf < 4; nf++) {
                    int nt = nf >> 1, q = (nf & 1) * 2;
                    MMA16816(acc[mt][nf], ah[mt], bh[nt][q], bh[nt][q + 1]);
                }
            }
        }

        if (c + 2 < nk) {
            __syncthreads();
            load_chunk(c + 2);
        }
    }

#pragma unroll
    for (int mt = 0; mt < 4; mt++) {
#pragma unroll
        for (int nf = 0; nf < 4; nf++) {
            int col = n0 + wn * 32 + nf * 8 + (lane & 3) * 2;
            if (col >= O) continue;
            int row0 = m0 + wm * 64 + mt * 16 + (lane >> 2);
            float bi0 = bias[col], bi1 = bias[col + 1];
#pragma unroll
            for (int i = 0; i < 2; i++) {
                size_t r = row0 + i * 8;
                float v0 = acc[mt][nf][i * 2 + 0] + bi0;
                float v1 = acc[mt][nf][i * 2 + 1] + bi1;
                if (OUT_MODE == 0) {
                    *(float2*)&Yf[r * O + col] = make_float2(v0, v1);
                } else {
                    v0 = fmaxf(v0, 0.f); v1 = fmaxf(v1, 0.f);
                    *(__half2*)&Yh[r * O + col] =
                        __halves2half2(__float2half(v0), __float2half(v1));
                }
            }
        }
    }
}

// ---------------- embed (x0 plain fp32; x0h swizzled-tiled fp16) ----------------
__global__ void embed_kernel(const int* __restrict__ inputs,
                             const float* __restrict__ emb,
                             const float* __restrict__ pos,
                             float* __restrict__ x0,
                             f16* __restrict__ x0h) {
    int idx = blockIdx.x * blockDim.x + threadIdx.x;
    if (idx >= NTOK * (HD / 4)) return;
    int tok = idx >> 5;
    int c   = idx & 31;
    int t   = tok % TT;
    int w   = inputs[tok];
    float4 e = ((const float4*)emb)[(long)w * 32 + c];
    float4 p = ((const float4*)pos)[t * 32 + c];
    float4 r;
    r.x = e.x + p.x; r.y = e.y + p.y; r.z = e.z + p.z; r.w = e.w + p.w;
    ((float4*)x0)[idx] = r;
    __half2 h0 = __halves2half2(__float2half(r.x), __float2half(r.y));
    __half2 h1 = __halves2half2(__float2half(r.z), __float2half(r.w));
    uint32_t byte = (uint32_t)(tok & 127) * 256 + c * 8;
    size_t el = (size_t)(tok >> 7) * TILE_ELEMS + (SWZ(byte) >> 1);
    *(__half2*)&x0h[el]     = h0;
    *(__half2*)&x0h[el + 2] = h1;
}

// ---------------- weight conversion: fp32 -> fp16, swizzled-tiled for K=128 mats ----------------
__global__ void convert_all(const float* w0, const float* w1, const float* w2,
                            const float* w3, const float* w4, const float* w5,
                            const float* w6, const float* w7, const float* w8,
                            const float* w9, f16* __restrict__ h) {
    int i = blockIdx.x * blockDim.x + threadIdx.x;
    if (i >= SRC_TOT) return;
    const float* s; int off;
    int dstBase;
    int row, col;
    if (i < SRC_PROJ) {                        // QKV: 6 mats of 96x128 packed -> 576 rows
        int seg = i / 12288; off = i - seg * 12288;
        s = seg == 0 ? w0 : seg == 1 ? w1 : seg == 2 ? w2 : seg == 3 ? w3 : seg == 4 ? w4 : w5;
        row = seg * 96 + (off >> 7); col = off & 127;
        dstBase = W_QKV;
    } else if (i < SRC_FF1) {                  // PROJ 128x192 plain
        s = w6; off = i - SRC_PROJ;
        h[W_PROJ + off] = __float2half(s[off]);
        return;
    } else if (i < SRC_FF2) {                  // FF1 2048x128
        s = w7; off = i - SRC_FF1;
        row = off >> 7; col = off & 127;
        dstBase = W_FF1;
    } else if (i < SRC_FIN) {                  // FF2 128x2048 plain
        s = w8; off = i - SRC_FF2;
        h[W_FF2 + off] = __float2half(s[off]);
        return;
    } else {                                   // FIN 8000x128
        s = w9; off = i - SRC_FIN;
        row = off >> 7; col = off & 127;
        dstBase = W_FIN;
    }
    uint32_t byte = (uint32_t)(row & 127) * 256 + col * 2;
    size_t el = (size_t)dstBase + (size_t)(row >> 7) * TILE_ELEMS + (SWZ(byte) >> 1);
    h[el] = __float2half(s[off]);
}

__global__ void pack_bias(const float* b0, const float* b1, const float* b2,
                          const float* b3, const float* b4, const float* b5,
                          float* __restrict__ out) {
    int i = threadIdx.x;
    if (i >= QKVW) return;
    int seg = i / DK, j = i % DK;
    const float* s = seg == 0 ? b0 : seg == 1 ? b1 : seg == 2 ? b2 : seg == 3 ? b3 : seg == 4 ? b4 : b5;
    out[i] = s[j];
}

// ---------------- attention (both heads, from packed qkv [NTOK,576]) ----------------
__global__ __launch_bounds__(256)
void attn_kernel(const float* __restrict__ qkv, f16* __restrict__ h12h) {
    __shared__ float sq[TT * DKP];
    __shared__ float sk[TT * DKP];
    __shared__ float ss[TT * SSP];
    int n = blockIdx.x;
    int head = blockIdx.y;
    int tid = threadIdx.x;
    int ko = head * 288, vo = 96 + head * 288, qo = 192 + head * 288;
    const float* base = qkv + (size_t)n * TT * QKVW;

    for (int i = tid; i < TT * 24; i += 256) {
        int t = i / 24, c4 = (i % 24) * 4;
        float4 a = *(const float4*)(base + (size_t)t * QKVW + qo + c4);
        float4 b = *(const float4*)(base + (size_t)t * QKVW + ko + c4);
        sq[t * DKP + c4 + 0] = a.x; sq[t * DKP + c4 + 1] = a.y;
        sq[t * DKP + c4 + 2] = a.z; sq[t * DKP + c4 + 3] = a.w;
        sk[t * DKP + c4 + 0] = b.x; sk[t * DKP + c4 + 1] = b.y;
        sk[t * DKP + c4 + 2] = b.z; sk[t * DKP + c4 + 3] = b.w;
    }
    __syncthreads();

    const float scale = rsqrtf((float)DK);
    for (int idx = tid; idx < TT * TT; idx += 256) {
        int t = idx / TT, s = idx % TT;
        float acc = 0.f;
#pragma unroll 8
        for (int d = 0; d < DK; d++) acc += sq[t * DKP + d] * sk[s * DKP + d];
        ss[t * SSP + s] = acc * scale;
    }
    __syncthreads();

    for (int i = tid; i < TT * 24; i += 256) {
        int t = i / 24, c4 = (i % 24) * 4;
        float4 a = *(const float4*)(base + (size_t)t * QKVW + vo + c4);
        sq[t * DKP + c4 + 0] = a.x; sq[t * DKP + c4 + 1] = a.y;
        sq[t * DKP + c4 + 2] = a.z; sq[t * DKP + c4 + 3] = a.w;
    }
    int wid = tid >> 5, lane = tid & 31;
    for (int t = wid; t < TT; t += 8) {
        float m = -1e30f;
        for (int s = lane; s < TT; s += 32) m = fmaxf(m, ss[t * SSP + s]);
#pragma unroll
        for (int o = 16; o; o >>= 1) m = fmaxf(m, __shfl_xor_sync(0xffffffffu, m, o));
        float sum = 0.f;
        for (int s = lane; s < TT; s += 32) {
            float e = __expf(ss[t * SSP + s] - m);
            ss[t * SSP + s] = e;
            sum += e;
        }
#pragma unroll
        for (int o = 16; o; o >>= 1) sum += __shfl_xor_sync(0xffffffffu, sum, o);
        float inv = 1.f / sum;
        for (int s = lane; s < TT; s += 32) ss[t * SSP + s] *= inv;
    }
    __syncthreads();

    for (int idx = tid; idx < TT * DK; idx += 256) {
        int t = idx / DK, d = idx % DK;
        float acc = 0.f;
#pragma unroll 43
        for (int s = 0; s < TT; s++) acc += ss[t * SSP + s] * sq[s * DKP + d];
        h12h[(size_t)(n * TT + t) * (2 * DK) + head * DK + d] = __float2half(acc);
    }
}

// ---------------- add residual + LayerNorm (fp32 plain + swizzled-tiled fp16) ----------------
__global__ __launch_bounds__(128)
void add_ln_kernel(const float* __restrict__ y, const float* __restrict__ r,
                   const float* __restrict__ g, const float* __restrict__ b,
                   float* __restrict__ o, f16* __restrict__ oh) {
    long row = blockIdx.x;
    int h = threadIdx.x;
    __shared__ float red[8];
    float v = y[row * HD + h] + r[row * HD + h];
    float s = v;
#pragma unroll
    for (int off = 16; off; off >>= 1) s += __shfl_xor_sync(0xffffffffu, s, off);
    int wid = h >> 5, lane = h & 31;
    if (!lane) red[wid] = s;
    __syncthreads();
    float mean = (red[0] + red[1] + red[2] + red[3]) * (1.f / HD);
    float d = v - mean;
    float s2 = d * d;
#pragma unroll
    for (int off = 16; off; off >>= 1) s2 += __shfl_xor_sync(0xffffffffu, s2, off);
    if (!lane) red[4 + wid] = s2;
    __syncthreads();
    float var = (red[4] + red[5] + red[6] + red[7]) * (1.f / HD);
    float out = d * rsqrtf(var + LNEPS) * g[h] + b[h];
    if (o) o[row * HD + h] = out;
    uint32_t byte = (uint32_t)(row & 127) * 256 + h * 2;
    size_t el = (size_t)(row >> 7) * TILE_ELEMS + (SWZ(byte) >> 1);
    oh[el] = __float2half(out);
}

// ---------------- host launch ----------------
extern "C" void kernel_launch(void* const* d_in, const int* in_sizes, int n_in,
                              void* d_out, int out_size) {
    const int*   inputs = (const int*)  d_in[0];
    const float* emb    = (const float*)d_in[1];
    const float* pos    = (const float*)d_in[2];
    const float* Wk1 = (const float*)d_in[3],  *bk1 = (const float*)d_in[4];
    const float* Wv1 = (const float*)d_in[5],  *bv1 = (const float*)d_in[6];
    const float* Wq1 = (const float*)d_in[7],  *bq1 = (const float*)d_in[8];
    const float* Wk2 = (const float*)d_in[9],  *bk2 = (const float*)d_in[10];
    const float* Wv2 = (const float*)d_in[11], *bv2 = (const float*)d_in[12];
    const float* Wq2 = (const float*)d_in[13], *bq2 = (const float*)d_in[14];
    const float* Wproj = (const float*)d_in[15], *bproj = (const float*)d_in[16];
    const float* gmh   = (const float*)d_in[17], *bmh   = (const float*)d_in[18];
    const float* Wff1  = (const float*)d_in[19], *bff1  = (const float*)d_in[20];
    const float* Wff2  = (const float*)d_in[21], *bff2  = (const float*)d_in[22];
    const float* gff   = (const float*)d_in[23], *bffb  = (const float*)d_in[24];
    const float* Wfin  = (const float*)d_in[25], *bfin  = (const float*)d_in[26];
    float* out = (float*)d_out;

    float *x0, *qkv, *bqkv, *mho, *x1, *ff2;
    f16 *x0h, *h12h, *x1h, *ffhh, *x2h, *wh;
    cudaGetSymbolAddress((void**)&x0,   g_x0);
    cudaGetSymbolAddress((void**)&x0h,  g_x0h);
    cudaGetSymbolAddress((void**)&qkv,  g_qkv);
    cudaGetSymbolAddress((void**)&bqkv, g_bqkv);
    cudaGetSymbolAddress((void**)&h12h, g_h12h);
    cudaGetSymbolAddress((void**)&mho,  g_mho);
    cudaGetSymbolAddress((void**)&x1,   g_x1);
    cudaGetSymbolAddress((void**)&x1h,  g_x1h);
    cudaGetSymbolAddress((void**)&ffhh, g_ffhh);
    cudaGetSymbolAddress((void**)&ff2,  g_ff2);
    cudaGetSymbolAddress((void**)&x2h,  g_x2h);
    cudaGetSymbolAddress((void**)&wh,   g_wh);

    cudaFuncSetAttribute(gemm_bt<0>, cudaFuncAttributeMaxDynamicSharedMemorySize, SMEM_BYTES);
    cudaFuncSetAttribute(gemm_k128s<0>, cudaFuncAttributeMaxDynamicSharedMemorySize, K128S_SMEM);
    cudaFuncSetAttribute(gemm_k128s<1>, cudaFuncAttributeMaxDynamicSharedMemorySize, K128S_SMEM);

    const int MB = NTOK / 128;   // 172

    convert_all<<<(SRC_TOT + 255) / 256, 256>>>(Wk1, Wv1, Wq1, Wk2, Wv2, Wq2,
                                                Wproj, Wff1, Wff2, Wfin, wh);
    pack_bias<<<1, QKVW>>>(bk1, bv1, bq1, bk2, bv2, bq2, bqkv);
    embed_kernel<<<(NTOK * 32 + 255) / 256, 256>>>(inputs, emb, pos, x0, x0h);

    // fused QKV (both heads): [NTOK,576] = x0 @ Wqkv^T + b   (K=128 streaming)
    gemm_k128s<0><<<dim3(5, 57), 256, K128S_SMEM>>>(x0h, wh + W_QKV, bqkv,
                                                    qkv, nullptr, NTOK, QKVW, 57);
    attn_kernel<<<dim3(NB, 2), 256>>>(qkv, h12h);

    gemm_bt<0><<<dim3(1, MB), 256, SMEM_BYTES>>>(h12h, wh + W_PROJ, bproj,
                                                 mho, nullptr, NTOK, 2 * DK, HD);
    add_ln_kernel<<<NTOK, 128>>>(mho, x0, gmh, bmh, x1, x1h);

    gemm_k128s<1><<<dim3(16, 18), 256, K128S_SMEM>>>(x1h, wh + W_FF1, bff1,
                                                     nullptr, ffhh, NTOK, DFF, 18);
    gemm_bt<0><<<dim3(1, MB), 256, SMEM_BYTES>>>(ffhh, wh + W_FF2, bff2,
                                                 ff2, nullptr, NTOK, DFF, HD);
    add_ln_kernel<<<NTOK, 128>>>(ff2, x1, gff, bffb, nullptr, x2h);

    gemm_k128s<0><<<dim3(63, 5), 256, K128S_SMEM>>>(x2h, wh + W_FIN, bfin,
                                                    out, nullptr, NTOK, OUTV, 5);
}

// round 16
// speedup vs baseline: 1.2724x; 1.2724x over previous
#include <cuda_runtime.h>
#include <cuda_fp16.h>
#include <cstdint>

typedef __half f16;

#define NTOK 22016   // 512*43
#define NB   512
#define TT   43
#define HD   128
#define DK   96
#define DKP  97
#define SSP  44
#define DFF  2048
#define OUTV 8000
#define QKVW 576
#define LNEPS 1e-5f

// source (input) packed weight offsets
#define SRC_PROJ 73728
#define SRC_FF1  98304
#define SRC_FF2  360448
#define SRC_FIN  622592
#define SRC_TOT  1646592

// destination layout in g_wh (tile-aligned; QKV/FF1/FIN swizzled-tiled, PROJ/FF2 plain)
#define TILE_ELEMS 16384
#define TILE_BYTES 32768
#define W_QKV  0          // 5 tiles  (576 rows -> 640 padded)
#define W_PROJ 81920      // plain 24576
#define W_FF1  114688     // 16 tiles (2048 rows)
#define W_FF2  376832     // plain 262144
#define W_FIN  638976     // 63 tiles (8000 rows -> 8064 padded)
#define W_TOT  1671168

// XOR swizzle for 256B rows: bits[4:7) ^= bits[8:11)
#define SWZ(x) ((x) ^ ((((x) >> 8) & 7) << 4))

// ---------------- scratch (device globals) ----------------
__device__ float g_x0 [NTOK * HD];
__device__ f16   g_x0h[NTOK * HD];          // swizzled-tiled
__device__ float g_qkv[NTOK * QKVW];
__device__ float g_bqkv[QKVW];
__device__ f16   g_h12h[NTOK * 2 * DK];     // plain
__device__ float g_mho[NTOK * HD];
__device__ float g_x1 [NTOK * HD];
__device__ f16   g_x1h[NTOK * HD];          // swizzled-tiled
__device__ f16   g_ffhh[NTOK * DFF];        // plain
__device__ float g_ff2p[4 * NTOK * HD];     // split-K partials
__device__ f16   g_x2h[NTOK * HD];          // swizzled-tiled
__device__ f16   g_wh[W_TOT];

// ---------------- helpers ----------------
__device__ __forceinline__ uint32_t smem_u32(const void* p) {
    return (uint32_t)__cvta_generic_to_shared(p);
}

#define LDMX4(R, ADDR) \
    asm volatile("ldmatrix.sync.aligned.m8n8.x4.shared.b16 {%0,%1,%2,%3},[%4];\n" \
        : "=r"((R)[0]), "=r"((R)[1]), "=r"((R)[2]), "=r"((R)[3]) : "r"(ADDR))

#define MMA16816(C, A, B0, B1) \
    asm volatile("mma.sync.aligned.m16n8k16.row.col.f32.f16.f16.f32 " \
        "{%0,%1,%2,%3},{%4,%5,%6,%7},{%8,%9},{%0,%1,%2,%3};\n" \
        : "+f"((C)[0]), "+f"((C)[1]), "+f"((C)[2]), "+f"((C)[3]) \
        : "r"((A)[0]), "r"((A)[1]), "r"((A)[2]), "r"((A)[3]), "r"(B0), "r"(B1))

__device__ __forceinline__ void cpa16(uint32_t saddr, const void* gaddr, int srcsz) {
    asm volatile("cp.async.cg.shared.global [%0], [%1], 16, %2;\n"
                 :: "r"(saddr), "l"(gaddr), "r"(srcsz) : "memory");
}
#define CPA_COMMIT() asm volatile("cp.async.commit_group;\n" ::: "memory")
#define CPA_WAITG(n) asm volatile("cp.async.wait_group %0;\n" :: "n"(n) : "memory")

// ============ bulk-copy GEMM for K=128: Y[M,O] = X[M,128] @ W[O,128]^T + b ============
// A,B pre-swizzled tile-major in gmem (tile = 128 rows x 256B, SWZ within tile).
// One 128x128 output tile per CTA: 2 bulk copies + 1 mbarrier.
// 256 threads (8 warps 2x4), warp tile 64x32, 64KB smem -> 2 CTAs/SM.
#define K128_SMEM (2 * TILE_BYTES + 16)

template<int OUT_MODE>
__global__ __launch_bounds__(256, 2)
void gemm_k128(const f16* __restrict__ A, const f16* __restrict__ B,
               const float* __restrict__ bias,
               float* __restrict__ Yf, f16* __restrict__ Yh, int O) {
    extern __shared__ char smem[];
    const uint32_t sAb = smem_u32(smem);
    const uint32_t sBb = sAb + TILE_BYTES;
    const uint32_t mb  = sAb + 2 * TILE_BYTES;
    const int tid = threadIdx.x;
    const int wid = tid >> 5, lane = tid & 31;
    const int wm = wid & 1, wn = wid >> 1;     // 2 x 4 warps, warp tile 64x32
    const int m0 = blockIdx.y << 7;
    const int n0 = blockIdx.x << 7;

    if (tid == 0)
        asm volatile("mbarrier.init.shared.b64 [%0], 1;" :: "r"(mb) : "memory");
    __syncthreads();
    if (tid == 0) {
        asm volatile("mbarrier.arrive.expect_tx.shared.b64 _, [%0], %1;"
                     :: "r"(mb), "r"(2 * TILE_BYTES) : "memory");
        const void* gA = A + (size_t)blockIdx.y * TILE_ELEMS;
        const void* gB = B + (size_t)blockIdx.x * TILE_ELEMS;
        asm volatile("cp.async.bulk.shared::cta.global.mbarrier::complete_tx::bytes "
                     "[%0], [%1], %2, [%3];"
                     :: "r"(sAb), "l"(gA), "r"(TILE_BYTES), "r"(mb) : "memory");
        asm volatile("cp.async.bulk.shared::cta.global.mbarrier::complete_tx::bytes "
                     "[%0], [%1], %2, [%3];"
                     :: "r"(sBb), "l"(gB), "r"(TILE_BYTES), "r"(mb) : "memory");
    }
    {
        unsigned done = 0;
        while (!done) {
            asm volatile("{\n\t.reg .pred p;\n\t"
                         "mbarrier.test_wait.parity.shared.b64 p, [%1], %2;\n\t"
                         "selp.u32 %0, 1, 0, p;\n\t}"
                         : "=r"(done) : "r"(mb), "r"(0u) : "memory");
        }
    }

    float acc[4][4][4];
#pragma unroll
    for (int a = 0; a < 4; a++)
#pragma unroll
        for (int b = 0; b < 4; b++)
#pragma unroll
            for (int c = 0; c < 4; c++) acc[a][b][c] = 0.f;

#pragma unroll
    for (int ks = 0; ks < 128; ks += 16) {
        unsigned ah[4][4], bh[2][4];
#pragma unroll
        for (int mt = 0; mt < 4; mt++) {
            int row = wm * 64 + mt * 16 + (lane & 15);
            int cb = (ks + (lane >> 4) * 8) * 2;
            LDMX4(ah[mt], sAb + SWZ(row * 256 + cb));
        }
#pragma unroll
        for (int nt = 0; nt < 2; nt++) {
            int row = wn * 32 + nt * 16 + (lane & 7) + ((lane >> 4) << 3);
            int cb = (ks + ((lane >> 3) & 1) * 8) * 2;
            LDMX4(bh[nt], sBb + SWZ(row * 256 + cb));
        }
#pragma unroll
        for (int mt = 0; mt < 4; mt++) {
#pragma unroll
            for (int nf = 0; nf < 4; nf++) {
                int nt = nf >> 1, q = (nf & 1) * 2;
                MMA16816(acc[mt][nf], ah[mt], bh[nt][q], bh[nt][q + 1]);
            }
        }
    }

#pragma unroll
    for (int mt = 0; mt < 4; mt++) {
#pragma unroll
        for (int nf = 0; nf < 4; nf++) {
            int col = n0 + wn * 32 + nf * 8 + (lane & 3) * 2;
            if (col >= O) continue;
            int row0 = m0 + wm * 64 + mt * 16 + (lane >> 2);
            float bi0 = bias[col], bi1 = bias[col + 1];
#pragma unroll
            for (int i = 0; i < 2; i++) {
                size_t r = row0 + i * 8;
                float v0 = acc[mt][nf][i * 2 + 0] + bi0;
                float v1 = acc[mt][nf][i * 2 + 1] + bi1;
                if (OUT_MODE == 0) {
                    *(float2*)&Yf[r * O + col] = make_float2(v0, v1);
                } else {
                    v0 = fmaxf(v0, 0.f); v1 = fmaxf(v1, 0.f);
                    *(__half2*)&Yh[r * O + col] =
                        __halves2half2(__float2half(v0), __float2half(v1));
                }
            }
        }
    }
}

// ============ generic pipelined fp16 GEMM, plain inputs ============
// OUT_MODE 0: fp32 + bias.  OUT_MODE 2: fp32 raw (split-K partial, no bias),
// output offset by blockIdx.z * M * O; K-range = [blockIdx.z*kLen, +kLen).
#define ROWB   144
#define B_OFF  18432
#define STAGE  36864
#define SMEM_BYTES (2 * STAGE)

template<int OUT_MODE>
__global__ __launch_bounds__(256, 2)
void gemm_bt(const f16* __restrict__ Ah, const f16* __restrict__ Bh,
             const float* __restrict__ bias,
             float* __restrict__ Yf, f16* __restrict__ Yh,
             int M, int K, int O, int kLen) {
    extern __shared__ char smem[];
    const uint32_t sbd = smem_u32(smem);
    const int tid = threadIdx.x;
    const int wid = tid >> 5, lane = tid & 31;
    const int wm = wid & 1, wn = wid >> 1;       // 2 x 4 warps, warp tile 64x32
    const int m0 = blockIdx.y << 7;
    const int n0 = blockIdx.x << 7;
    const int kOff = blockIdx.z * kLen;
    const int nk = kLen >> 6;
    float* Yout = (OUT_MODE == 2) ? Yf + (size_t)blockIdx.z * M * O : Yf;

    float acc[4][4][4];
#pragma unroll
    for (int a = 0; a < 4; a++)
#pragma unroll
        for (int b = 0; b < 4; b++)
#pragma unroll
            for (int c = 0; c < 4; c++) acc[a][b][c] = 0.f;

    auto load_chunk = [&](int c) {
        uint32_t stage = sbd + (c & 1) * STAGE;
        int kk = kOff + (c << 6);
#pragma unroll
        for (int i = 0; i < 4; i++) {
            int idx = tid + (i << 8);
            int row = idx >> 3, c8 = idx & 7;
            cpa16(stage + row * ROWB + c8 * 16, Ah + (size_t)(m0 + row) * K + kk + c8 * 8, 16);
        }
#pragma unroll
        for (int i = 0; i < 4; i++) {
            int idx = tid + (i << 8);
            int row = idx >> 3, c8 = idx & 7;
            int gr = n0 + row;
            int sz = 16;
            if (gr >= O) { sz = 0; gr = 0; }
            cpa16(stage + B_OFF + row * ROWB + c8 * 16, Bh + (size_t)gr * K + kk + c8 * 8, sz);
        }
        CPA_COMMIT();
    };

    load_chunk(0);
    load_chunk(1);

    for (int c = 0; c < nk; c++) {
        if (c < nk - 1) { CPA_WAITG(1); } else { CPA_WAITG(0); }
        __syncthreads();

        uint32_t stage = sbd + (c & 1) * STAGE;
#pragma unroll
        for (int ks = 0; ks < 64; ks += 16) {
            unsigned ah[4][4], bh[2][4];
#pragma unroll
            for (int mt = 0; mt < 4; mt++) {
                int row = wm * 64 + mt * 16 + (lane & 15);
                int cb = (ks + (lane >> 4) * 8) * 2;
                LDMX4(ah[mt], stage + row * ROWB + cb);
            }
#pragma unroll
            for (int nt = 0; nt < 2; nt++) {
                int row = wn * 32 + nt * 16 + (lane & 7) + ((lane >> 4) << 3);
                int cb = (ks + ((lane >> 3) & 1) * 8) * 2;
                LDMX4(bh[nt], stage + B_OFF + row * ROWB + cb);
            }
#pragma unroll
            for (int mt = 0; mt < 4; mt++) {
#pragma unroll
                for (int nf = 0; nf < 4; nf++) {
                    int nt = nf >> 1, q = (nf & 1) * 2;
                    MMA16816(acc[mt][nf], ah[mt], bh[nt][q], bh[nt][q + 1]);
                }
            }
        }

        if (c + 2 < nk) {
            __syncthreads();
            load_chunk(c + 2);
        }
    }

#pragma unroll
    for (int mt = 0; mt < 4; mt++) {
#pragma unroll
        for (int nf = 0; nf < 4; nf++) {
            int col = n0 + wn * 32 + nf * 8 + (lane & 3) * 2;
            if (col >= O) continue;
            int row0 = m0 + wm * 64 + mt * 16 + (lane >> 2);
            float bi0 = 0.f, bi1 = 0.f;
            if (OUT_MODE == 0) { bi0 = bias[col]; bi1 = bias[col + 1]; }
#pragma unroll
            for (int i = 0; i < 2; i++) {
                size_t r = row0 + i * 8;
                float v0 = acc[mt][nf][i * 2 + 0] + bi0;
                float v1 = acc[mt][nf][i * 2 + 1] + bi1;
                *(float2*)&Yout[r * O + col] = make_float2(v0, v1);
            }
        }
    }
}

// ---------------- embed (x0 plain fp32; x0h swizzled-tiled fp16) ----------------
__global__ void embed_kernel(const int* __restrict__ inputs,
                             const float* __restrict__ emb,
                             const float* __restrict__ pos,
                             float* __restrict__ x0,
                             f16* __restrict__ x0h) {
    int idx = blockIdx.x * blockDim.x + threadIdx.x;
    if (idx >= NTOK * (HD / 4)) return;
    int tok = idx >> 5;
    int c   = idx & 31;
    int t   = tok % TT;
    int w   = inputs[tok];
    float4 e = ((const float4*)emb)[(long)w * 32 + c];
    float4 p = ((const float4*)pos)[t * 32 + c];
    float4 r;
    r.x = e.x + p.x; r.y = e.y + p.y; r.z = e.z + p.z; r.w = e.w + p.w;
    ((float4*)x0)[idx] = r;
    __half2 h0 = __halves2half2(__float2half(r.x), __float2half(r.y));
    __half2 h1 = __halves2half2(__float2half(r.z), __float2half(r.w));
    uint32_t byte = (uint32_t)(tok & 127) * 256 + c * 8;
    size_t el = (size_t)(tok >> 7) * TILE_ELEMS + (SWZ(byte) >> 1);
    *(__half2*)&x0h[el]     = h0;
    *(__half2*)&x0h[el + 2] = h1;
}

// ---------------- weight conversion: fp32 -> fp16, swizzled-tiled for K=128 mats ----------------
__global__ void convert_all(const float* w0, const float* w1, const float* w2,
                            const float* w3, const float* w4, const float* w5,
                            const float* w6, const float* w7, const float* w8,
                            const float* w9, f16* __restrict__ h) {
    int i = blockIdx.x * blockDim.x + threadIdx.x;
    if (i >= SRC_TOT) return;
    const float* s; int off;
    int dstBase;
    int row, col;
    if (i < SRC_PROJ) {                        // QKV: 6 mats of 96x128 packed -> 576 rows
        int seg = i / 12288; off = i - seg * 12288;
        s = seg == 0 ? w0 : seg == 1 ? w1 : seg == 2 ? w2 : seg == 3 ? w3 : seg == 4 ? w4 : w5;
        row = seg * 96 + (off >> 7); col = off & 127;
        dstBase = W_QKV;
    } else if (i < SRC_FF1) {                  // PROJ 128x192 plain
        s = w6; off = i - SRC_PROJ;
        h[W_PROJ + off] = __float2half(s[off]);
        return;
    } else if (i < SRC_FF2) {                  // FF1 2048x128
        s = w7; off = i - SRC_FF1;
        row = off >> 7; col = off & 127;
        dstBase = W_FF1;
    } else if (i < SRC_FIN) {                  // FF2 128x2048 plain
        s = w8; off = i - SRC_FF2;
        h[W_FF2 + off] = __float2half(s[off]);
        return;
    } else {                                   // FIN 8000x128
        s = w9; off = i - SRC_FIN;
        row = off >> 7; col = off & 127;
        dstBase = W_FIN;
    }
    uint32_t byte = (uint32_t)(row & 127) * 256 + col * 2;
    size_t el = (size_t)dstBase + (size_t)(row >> 7) * TILE_ELEMS + (SWZ(byte) >> 1);
    h[el] = __float2half(s[off]);
}

__global__ void pack_bias(const float* b0, const float* b1, const float* b2,
                          const float* b3, const float* b4, const float* b5,
                          float* __restrict__ out) {
    int i = threadIdx.x;
    if (i >= QKVW) return;
    int seg = i / DK, j = i % DK;
    const float* s = seg == 0 ? b0 : seg == 1 ? b1 : seg == 2 ? b2 : seg == 3 ? b3 : seg == 4 ? b4 : b5;
    out[i] = s[j];
}

// ---------------- attention (both heads, from packed qkv [NTOK,576]) ----------------
__global__ __launch_bounds__(256)
void attn_kernel(const float* __restrict__ qkv, f16* __restrict__ h12h) {
    __shared__ float sq[TT * DKP];
    __shared__ float sk[TT * DKP];
    __shared__ float ss[TT * SSP];
    int n = blockIdx.x;
    int head = blockIdx.y;
    int tid = threadIdx.x;
    int ko = head * 288, vo = 96 + head * 288, qo = 192 + head * 288;
    const float* base = qkv + (size_t)n * TT * QKVW;

    for (int i = tid; i < TT * 24; i += 256) {
        int t = i / 24, c4 = (i % 24) * 4;
        float4 a = *(const float4*)(base + (size_t)t * QKVW + qo + c4);
        float4 b = *(const float4*)(base + (size_t)t * QKVW + ko + c4);
        sq[t * DKP + c4 + 0] = a.x; sq[t * DKP + c4 + 1] = a.y;
        sq[t * DKP + c4 + 2] = a.z; sq[t * DKP + c4 + 3] = a.w;
        sk[t * DKP + c4 + 0] = b.x; sk[t * DKP + c4 + 1] = b.y;
        sk[t * DKP + c4 + 2] = b.z; sk[t * DKP + c4 + 3] = b.w;
    }
    __syncthreads();

    const float scale = rsqrtf((float)DK);
    for (int idx = tid; idx < TT * TT; idx += 256) {
        int t = idx / TT, s = idx % TT;
        float acc = 0.f;
#pragma unroll 8
        for (int d = 0; d < DK; d++) acc += sq[t * DKP + d] * sk[s * DKP + d];
        ss[t * SSP + s] = acc * scale;
    }
    __syncthreads();

    for (int i = tid; i < TT * 24; i += 256) {
        int t = i / 24, c4 = (i % 24) * 4;
        float4 a = *(const float4*)(base + (size_t)t * QKVW + vo + c4);
        sq[t * DKP + c4 + 0] = a.x; sq[t * DKP + c4 + 1] = a.y;
        sq[t * DKP + c4 + 2] = a.z; sq[t * DKP + c4 + 3] = a.w;
    }
    int wid = tid >> 5, lane = tid & 31;
    for (int t = wid; t < TT; t += 8) {
        float m = -1e30f;
        for (int s = lane; s < TT; s += 32) m = fmaxf(m, ss[t * SSP + s]);
#pragma unroll
        for (int o = 16; o; o >>= 1) m = fmaxf(m, __shfl_xor_sync(0xffffffffu, m, o));
        float sum = 0.f;
        for (int s = lane; s < TT; s += 32) {
            float e = __expf(ss[t * SSP + s] - m);
            ss[t * SSP + s] = e;
            sum += e;
        }
#pragma unroll
        for (int o = 16; o; o >>= 1) sum += __shfl_xor_sync(0xffffffffu, sum, o);
        float inv = 1.f / sum;
        for (int s = lane; s < TT; s += 32) ss[t * SSP + s] *= inv;
    }
    __syncthreads();

    for (int idx = tid; idx < TT * DK; idx += 256) {
        int t = idx / DK, d = idx % DK;
        float acc = 0.f;
#pragma unroll 43
        for (int s = 0; s < TT; s++) acc += ss[t * SSP + s] * sq[s * DKP + d];
        h12h[(size_t)(n * TT + t) * (2 * DK) + head * DK + d] = __float2half(acc);
    }
}

// ---------------- add residual + LayerNorm (variant A: plain y) ----------------
__global__ __launch_bounds__(128)
void add_ln_kernel(const float* __restrict__ y, const float* __restrict__ r,
                   const float* __restrict__ g, const float* __restrict__ b,
                   float* __restrict__ o, f16* __restrict__ oh) {
    long row = blockIdx.x;
    int h = threadIdx.x;
    __shared__ float red[8];
    float v = y[row * HD + h] + r[row * HD + h];
    float s = v;
#pragma unroll
    for (int off = 16; off; off >>= 1) s += __shfl_xor_sync(0xffffffffu, s, off);
    int wid = h >> 5, lane = h & 31;
    if (!lane) red[wid] = s;
    __syncthreads();
    float mean = (red[0] + red[1] + red[2] + red[3]) * (1.f / HD);
    float d = v - mean;
    float s2 = d * d;
#pragma unroll
    for (int off = 16; off; off >>= 1) s2 += __shfl_xor_sync(0xffffffffu, s2, off);
    if (!lane) red[4 + wid] = s2;
    __syncthreads();
    float var = (red[4] + red[5] + red[6] + red[7]) * (1.f / HD);
    float out = d * rsqrtf(var + LNEPS) * g[h] + b[h];
    if (o) o[row * HD + h] = out;
    uint32_t byte = (uint32_t)(row & 127) * 256 + h * 2;
    size_t el = (size_t)(row >> 7) * TILE_ELEMS + (SWZ(byte) >> 1);
    oh[el] = __float2half(out);
}

// ---------------- variant B: y = sum of 4 split-K partials + ybias ----------------
__global__ __launch_bounds__(128)
void add_ln4_kernel(const float* __restrict__ p, const float* __restrict__ ybias,
                    const float* __restrict__ r,
                    const float* __restrict__ g, const float* __restrict__ b,
                    f16* __restrict__ oh) {
    long row = blockIdx.x;
    int h = threadIdx.x;
    __shared__ float red[8];
    size_t ix = row * HD + h;
    const size_t PS = (size_t)NTOK * HD;
    float v = p[ix] + p[ix + PS] + p[ix + 2 * PS] + p[ix + 3 * PS] + ybias[h] + r[ix];
    float s = v;
#pragma unroll
    for (int off = 16; off; off >>= 1) s += __shfl_xor_sync(0xffffffffu, s, off);
    int wid = h >> 5, lane = h & 31;
    if (!lane) red[wid] = s;
    __syncthreads();
    float mean = (red[0] + red[1] + red[2] + red[3]) * (1.f / HD);
    float d = v - mean;
    float s2 = d * d;
#pragma unroll
    for (int off = 16; off; off >>= 1) s2 += __shfl_xor_sync(0xffffffffu, s2, off);
    if (!lane) red[4 + wid] = s2;
    __syncthreads();
    float var = (red[4] + red[5] + red[6] + red[7]) * (1.f / HD);
    float out = d * rsqrtf(var + LNEPS) * g[h] + b[h];
    uint32_t byte = (uint32_t)(row & 127) * 256 + h * 2;
    size_t el = (size_t)(row >> 7) * TILE_ELEMS + (SWZ(byte) >> 1);
    oh[el] = __float2half(out);
}

// ---------------- host launch ----------------
extern "C" void kernel_launch(void* const* d_in, const int* in_sizes, int n_in,
                              void* d_out, int out_size) {
    const int*   inputs = (const int*)  d_in[0];
    const float* emb    = (const float*)d_in[1];
    const float* pos    = (const float*)d_in[2];
    const float* Wk1 = (const float*)d_in[3],  *bk1 = (const float*)d_in[4];
    const float* Wv1 = (const float*)d_in[5],  *bv1 = (const float*)d_in[6];
    const float* Wq1 = (const float*)d_in[7],  *bq1 = (const float*)d_in[8];
    const float* Wk2 = (const float*)d_in[9],  *bk2 = (const float*)d_in[10];
    const float* Wv2 = (const float*)d_in[11], *bv2 = (const float*)d_in[12];
    const float* Wq2 = (const float*)d_in[13], *bq2 = (const float*)d_in[14];
    const float* Wproj = (const float*)d_in[15], *bproj = (const float*)d_in[16];
    const float* gmh   = (const float*)d_in[17], *bmh   = (const float*)d_in[18];
    const float* Wff1  = (const float*)d_in[19], *bff1  = (const float*)d_in[20];
    const float* Wff2  = (const float*)d_in[21], *bff2  = (const float*)d_in[22];
    const float* gff   = (const float*)d_in[23], *bffb  = (const float*)d_in[24];
    const float* Wfin  = (const float*)d_in[25], *bfin  = (const float*)d_in[26];
    float* out = (float*)d_out;

    float *x0, *qkv, *bqkv, *mho, *x1, *ff2p;
    f16 *x0h, *h12h, *x1h, *ffhh, *x2h, *wh;
    cudaGetSymbolAddress((void**)&x0,   g_x0);
    cudaGetSymbolAddress((void**)&x0h,  g_x0h);
    cudaGetSymbolAddress((void**)&qkv,  g_qkv);
    cudaGetSymbolAddress((void**)&bqkv, g_bqkv);
    cudaGetSymbolAddress((void**)&h12h, g_h12h);
    cudaGetSymbolAddress((void**)&mho,  g_mho);
    cudaGetSymbolAddress((void**)&x1,   g_x1);
    cudaGetSymbolAddress((void**)&x1h,  g_x1h);
    cudaGetSymbolAddress((void**)&ffhh, g_ffhh);
    cudaGetSymbolAddress((void**)&ff2p, g_ff2p);
    cudaGetSymbolAddress((void**)&x2h,  g_x2h);
    cudaGetSymbolAddress((void**)&wh,   g_wh);

    cudaFuncSetAttribute(gemm_bt<0>, cudaFuncAttributeMaxDynamicSharedMemorySize, SMEM_BYTES);
    cudaFuncSetAttribute(gemm_bt<2>, cudaFuncAttributeMaxDynamicSharedMemorySize, SMEM_BYTES);
    cudaFuncSetAttribute(gemm_k128<0>, cudaFuncAttributeMaxDynamicSharedMemorySize, K128_SMEM);
    cudaFuncSetAttribute(gemm_k128<1>, cudaFuncAttributeMaxDynamicSharedMemorySize, K128_SMEM);

    const int MB = NTOK / 128;   // 172

    convert_all<<<(SRC_TOT + 255) / 256, 256>>>(Wk1, Wv1, Wq1, Wk2, Wv2, Wq2,
                                                Wproj, Wff1, Wff2, Wfin, wh);
    pack_bias<<<1, QKVW>>>(bk1, bv1, bq1, bk2, bv2, bq2, bqkv);
    embed_kernel<<<(NTOK * 32 + 255) / 256, 256>>>(inputs, emb, pos, x0, x0h);

    // fused QKV (both heads): [NTOK,576] = x0 @ Wqkv^T + b   (K=128, bulk-copy path)
    gemm_k128<0><<<dim3(5, MB), 256, K128_SMEM>>>(x0h, wh + W_QKV, bqkv,
                                                  qkv, nullptr, QKVW);
    attn_kernel<<<dim3(NB, 2), 256>>>(qkv, h12h);

    gemm_bt<0><<<dim3(1, MB), 256, SMEM_BYTES>>>(h12h, wh + W_PROJ, bproj,
                                                 mho, nullptr, NTOK, 2 * DK, HD, 2 * DK);
    add_ln_kernel<<<NTOK, 128>>>(mho, x0, gmh, bmh, x1, x1h);

    gemm_k128<1><<<dim3(16, MB), 256, K128_SMEM>>>(x1h, wh + W_FF1, bff1,
                                                   nullptr, ffhh, DFF);
    // FF2 split-K x4: each z computes K=512 partial into ff2p[z]
    gemm_bt<2><<<dim3(1, MB, 4), 256, SMEM_BYTES>>>(ffhh, wh + W_FF2, nullptr,
                                                    ff2p, nullptr, NTOK, DFF, HD, 512);
    add_ln4_kernel<<<NTOK, 128>>>(ff2p, bff2, x1, gff, bffb, x2h);

    gemm_k128<0><<<dim3(63, MB), 256, K128_SMEM>>>(x2h, wh + W_FIN, bfin,
                                                   out, nullptr, OUTV);
}